// round 2
// baseline (speedup 1.0000x reference)
#include <cuda_runtime.h>
#include <math.h>
#include <stdint.h>

// ---------------- problem constants ----------------
#define N_ROWS   131072
#define DIM      256
#define K_CODES  1024
#define EPS_F    1e-5f

// output layout (float32 elements), concatenated in reference return order
#define OFF_Q       0
#define OFF_LOSS    33554432
#define OFF_IDX     33554433
#define OFF_NEWEMB  33685505
#define OFF_NCS     33947649
#define OFF_NAVG    33948673
// total = 34210817

// ---------------- device scratch (no allocations allowed) ----------------
__device__ float  g_xx[N_ROWS];          // ||x||^2 per row
__device__ float  g_ee[K_CODES];         // ||e||^2 per code
__device__ float  g_counts[K_CODES];     // segment counts
__device__ float  g_embsum[K_CODES*DIM]; // segment sums
__device__ float  g_ncs[K_CODES];        // new cluster size
__device__ float  g_ntotal;              // sum(new_cluster_size) + eps
__device__ double g_sse;                 // sum of (q - x)^2
__device__ double g_ortho;               // ||E^T E||_F^2 accumulator

// ---------------- zero scratch (must run every replay) ----------------
__global__ void zero_scratch_kernel() {
    int i = blockIdx.x * blockDim.x + threadIdx.x;
    if (i < K_CODES*DIM) g_embsum[i] = 0.f;
    if (i < K_CODES)     g_counts[i] = 0.f;
    if (i == 0) { g_sse = 0.0; g_ortho = 0.0; }
}

// ---------------- row sum-of-squares: mode 0 -> g_xx, mode 1 -> g_ee ----------------
__global__ void rowsumsq_kernel(const float* __restrict__ src, int rows, int mode) {
    int warp = (blockIdx.x * blockDim.x + threadIdx.x) >> 5;
    int lane = threadIdx.x & 31;
    if (warp >= rows) return;
    const float4* p = (const float4*)(src + (size_t)warp * DIM);
    float s = 0.f;
    float4 v0 = p[lane];
    float4 v1 = p[lane + 32];
    s = fmaf(v0.x, v0.x, s); s = fmaf(v0.y, v0.y, s);
    s = fmaf(v0.z, v0.z, s); s = fmaf(v0.w, v0.w, s);
    s = fmaf(v1.x, v1.x, s); s = fmaf(v1.y, v1.y, s);
    s = fmaf(v1.z, v1.z, s); s = fmaf(v1.w, v1.w, s);
    #pragma unroll
    for (int o = 16; o > 0; o >>= 1) s += __shfl_xor_sync(0xffffffffu, s, o);
    if (lane == 0) {
        if (mode) g_ee[warp] = s; else g_xx[warp] = s;
    }
}

// ---------------- main fused kernel: distances + argmin + gather + scatter ----------------
// block: 256 threads, 128 rows x (loop over 8 tiles of 128 codes), 8x8 per-thread microtile
#define SLD 132   // smem row stride (floats): 16B-aligned rows, shifted banks
__global__ __launch_bounds__(256, 2)
void vq_main_kernel(const float* __restrict__ inp, const float* __restrict__ emb,
                    float* __restrict__ out)
{
    __shared__ __align__(16) float sX[32 * SLD];
    __shared__ __align__(16) float sE[32 * SLD];
    __shared__ float bestd[128];
    __shared__ int   besti[128];
    __shared__ double dred[256];

    const int tid = threadIdx.x;
    const int tx  = tid & 15;     // row-group selector
    const int ty  = tid >> 4;     // col-group selector
    const int R0  = blockIdx.x * 128;

    if (tid < 128) { bestd[tid] = 3.0e38f; besti[tid] = 0x7fffffff; }

    // rows / cols owned by this thread
    int mrow[8], ncol[8];
    #pragma unroll
    for (int q = 0; q < 4; q++) {
        mrow[q]     = tx * 4 + q;
        mrow[q + 4] = 64 + tx * 4 + q;
        ncol[q]     = ty * 4 + q;
        ncol[q + 4] = 64 + ty * 4 + q;
    }
    float xr[8];
    #pragma unroll
    for (int i = 0; i < 8; i++) xr[i] = g_xx[R0 + mrow[i]];

    const int ldrow = tid >> 3;          // 0..31
    const int ldkq  = (tid & 7) * 4;     // 0,4,...,28

    for (int n0 = 0; n0 < K_CODES; n0 += 128) {
        float acc[8][8];
        #pragma unroll
        for (int a = 0; a < 8; a++)
            #pragma unroll
            for (int b = 0; b < 8; b++) acc[a][b] = 0.f;

        for (int kc = 0; kc < DIM; kc += 32) {
            __syncthreads();   // smem free (prev chunk reads / reduction done)
            #pragma unroll
            for (int i = 0; i < 4; i++) {
                int m = ldrow + 32 * i;
                float4 v = *(const float4*)&inp[(size_t)(R0 + m) * DIM + kc + ldkq];
                sX[(ldkq + 0) * SLD + m] = v.x;
                sX[(ldkq + 1) * SLD + m] = v.y;
                sX[(ldkq + 2) * SLD + m] = v.z;
                sX[(ldkq + 3) * SLD + m] = v.w;
                float4 w = *(const float4*)&emb[(size_t)(n0 + m) * DIM + kc + ldkq];
                sE[(ldkq + 0) * SLD + m] = w.x;
                sE[(ldkq + 1) * SLD + m] = w.y;
                sE[(ldkq + 2) * SLD + m] = w.z;
                sE[(ldkq + 3) * SLD + m] = w.w;
            }
            __syncthreads();
            #pragma unroll 4
            for (int kk = 0; kk < 32; kk++) {
                float4 xa = *(const float4*)&sX[kk * SLD + tx * 4];
                float4 xb = *(const float4*)&sX[kk * SLD + 64 + tx * 4];
                float4 ea = *(const float4*)&sE[kk * SLD + ty * 4];
                float4 eb = *(const float4*)&sE[kk * SLD + 64 + ty * 4];
                float xf[8] = {xa.x, xa.y, xa.z, xa.w, xb.x, xb.y, xb.z, xb.w};
                float ef[8] = {ea.x, ea.y, ea.z, ea.w, eb.x, eb.y, eb.z, eb.w};
                #pragma unroll
                for (int mi = 0; mi < 8; mi++)
                    #pragma unroll
                    for (int ni = 0; ni < 8; ni++)
                        acc[mi][ni] = fmaf(xf[mi], ef[ni], acc[mi][ni]);
            }
        }

        // per-tile argmin epilogue (reference formula incl. ||x||^2 so fp grid matches)
        float ec[8];
        #pragma unroll
        for (int i = 0; i < 8; i++) ec[i] = g_ee[n0 + ncol[i]];

        __syncthreads();               // done reading sX this tile
        float* red_d = sX;             // alias: 128*16 floats
        int*   red_i = (int*)(sX + 2048);

        #pragma unroll
        for (int mi = 0; mi < 8; mi++) {
            float bd = 3.0e38f; int bi = 0x7fffffff;
            #pragma unroll
            for (int ni = 0; ni < 8; ni++) {
                float d = (xr[mi] + ec[ni]) - 2.0f * acc[mi][ni];
                int gi = n0 + ncol[ni];
                if (d < bd || (d == bd && gi < bi)) { bd = d; bi = gi; }
            }
            red_d[mrow[mi] * 16 + ty] = bd;
            red_i[mrow[mi] * 16 + ty] = bi;
        }
        __syncthreads();
        if (tid < 128) {
            float bd = bestd[tid]; int bi = besti[tid];
            #pragma unroll
            for (int j = 0; j < 16; j++) {
                float d = red_d[tid * 16 + j]; int gi = red_i[tid * 16 + j];
                if (d < bd || (d == bd && gi < bi)) { bd = d; bi = gi; }
            }
            bestd[tid] = bd; besti[tid] = bi;
        }
        // next iteration's leading __syncthreads() protects red buffer
    }
    __syncthreads();

    // indices output (as float)
    if (tid < 128) out[OFF_IDX + R0 + tid] = (float)besti[tid];

    // gather + quantized_st + mse + segment scatter
    double sse = 0.0;
    const float4* inp4 = (const float4*)inp;
    const float4* emb4 = (const float4*)emb;
    float4* out4 = (float4*)(out + OFF_Q);
    #pragma unroll 4
    for (int j = 0; j < 32; j++) {
        int e4  = tid + j * 256;       // 0..8191
        int r   = e4 >> 6;
        int c4  = e4 & 63;
        int idx = besti[r];
        float4 ev = emb4[idx * 64 + c4];
        float4 xv = inp4[(size_t)(R0 + r) * 64 + c4];
        float4 q;
        q.x = xv.x + (ev.x - xv.x);
        q.y = xv.y + (ev.y - xv.y);
        q.z = xv.z + (ev.z - xv.z);
        q.w = xv.w + (ev.w - xv.w);
        out4[(size_t)(R0 + r) * 64 + c4] = q;
        float d0 = ev.x - xv.x, d1 = ev.y - xv.y, d2 = ev.z - xv.z, d3 = ev.w - xv.w;
        sse += (double)d0 * d0 + (double)d1 * d1 + (double)d2 * d2 + (double)d3 * d3;
        float* es = &g_embsum[idx * DIM + c4 * 4];
        atomicAdd(es + 0, xv.x);
        atomicAdd(es + 1, xv.y);
        atomicAdd(es + 2, xv.z);
        atomicAdd(es + 3, xv.w);
        if (c4 == 0) atomicAdd(&g_counts[idx], 1.0f);
    }
    __syncthreads();
    dred[tid] = sse;
    __syncthreads();
    #pragma unroll
    for (int s = 128; s > 0; s >>= 1) {
        if (tid < s) dred[tid] += dred[tid + s];
        __syncthreads();
    }
    if (tid == 0) atomicAdd(&g_sse, dred[0]);
}

// ---------------- ortho via Gram trick: sum_{i,j}(e_i.e_j)^2 == ||E^T E||_F^2 ----------------
__global__ void gram_kernel(const float* __restrict__ emb) {
    __shared__ float sA[64][16];
    __shared__ float sB[64][16];
    __shared__ double sred[256];
    int tx = threadIdx.x & 15;
    int ty = threadIdx.x >> 4;
    int a0 = blockIdx.y * 16;
    int b0 = blockIdx.x * 16;
    float acc = 0.f;
    for (int k0 = 0; k0 < K_CODES; k0 += 64) {
        __syncthreads();
        #pragma unroll
        for (int i = 0; i < 4; i++) {
            int e = threadIdx.x + i * 256;
            int kr = e >> 4, c = e & 15;
            sA[kr][c] = emb[(size_t)(k0 + kr) * DIM + a0 + c];
            sB[kr][c] = emb[(size_t)(k0 + kr) * DIM + b0 + c];
        }
        __syncthreads();
        #pragma unroll 8
        for (int kk = 0; kk < 64; kk++)
            acc = fmaf(sA[kk][ty], sB[kk][tx], acc);
    }
    sred[threadIdx.x] = (double)acc * (double)acc;
    __syncthreads();
    #pragma unroll
    for (int s = 128; s > 0; s >>= 1) {
        if (threadIdx.x < s) sred[threadIdx.x] += sred[threadIdx.x + s];
        __syncthreads();
    }
    if (threadIdx.x == 0) atomicAdd(&g_ortho, sred[0]);
}

// ---------------- EMA finalize ----------------
__global__ void ema_a_kernel(const float* __restrict__ ema_cs, float* __restrict__ out) {
    __shared__ double sred[1024];
    int k = threadIdx.x;
    float ncs = 0.99f * ema_cs[k] + 0.01f * g_counts[k];
    out[OFF_NCS + k] = ncs;
    g_ncs[k] = ncs;
    sred[k] = (double)ncs;
    __syncthreads();
    #pragma unroll
    for (int s = 512; s > 0; s >>= 1) {
        if (k < s) sred[k] += sred[k + s];
        __syncthreads();
    }
    if (k == 0) g_ntotal = (float)sred[0] + EPS_F;
}

__global__ void ema_b_kernel(const float* __restrict__ ema_avg, float* __restrict__ out) {
    int k = blockIdx.x;
    int d = threadIdx.x;
    int i = k * DIM + d;
    float navg = 0.99f * ema_avg[i] + 0.01f * g_embsum[i];
    out[OFF_NAVG + i] = navg;
    float cs = (g_ncs[k] + EPS_F) / g_ntotal;
    out[OFF_NEWEMB + i] = navg / cs;
}

// ---------------- loss assembly ----------------
__global__ void loss_fin_kernel(float* __restrict__ out) {
    __shared__ double sred[256];
    double s = 0.0;
    for (int k = threadIdx.x; k < K_CODES; k += 256) {
        double e = (double)g_ee[k];
        s += e * e;
    }
    sred[threadIdx.x] = s;
    __syncthreads();
    #pragma unroll
    for (int t = 128; t > 0; t >>= 1) {
        if (threadIdx.x < t) sred[threadIdx.x] += sred[threadIdx.x + t];
        __syncthreads();
    }
    if (threadIdx.x == 0) {
        double o2 = g_ortho - sred[0];       // remove diagonal (e_i.e_i)^2 terms
        if (o2 < 0.0) o2 = 0.0;
        float ortho = sqrtf((float)o2);
        float m = (float)(g_sse / (double)((size_t)N_ROWS * DIM));
        // q_latent_loss == e_latent_loss numerically (stop_gradient is identity in value)
        out[OFF_LOSS] = (m + 0.25f * m) + 0.09f * ortho;
    }
}

// ---------------- launch ----------------
extern "C" void kernel_launch(void* const* d_in, const int* in_sizes, int n_in,
                              void* d_out, int out_size)
{
    const float* inp     = (const float*)d_in[0];  // [131072,256]
    const float* emb     = (const float*)d_in[1];  // [1024,256]
    const float* ema_cs  = (const float*)d_in[2];  // [1024]
    const float* ema_avg = (const float*)d_in[3];  // [1024,256]
    float* out = (float*)d_out;

    zero_scratch_kernel<<<K_CODES, 256>>>();
    rowsumsq_kernel<<<N_ROWS / 8, 256>>>(inp, N_ROWS, 0);
    rowsumsq_kernel<<<K_CODES / 8, 256>>>(emb, K_CODES, 1);
    vq_main_kernel<<<N_ROWS / 128, 256>>>(inp, emb, out);
    gram_kernel<<<dim3(16, 16), 256>>>(emb);
    ema_a_kernel<<<1, 1024>>>(ema_cs, out);
    ema_b_kernel<<<K_CODES, 256>>>(ema_avg, out);
    loss_fin_kernel<<<1, 256>>>(out);
}

// round 4
// speedup vs baseline: 1.7906x; 1.7906x over previous
#include <cuda_runtime.h>
#include <cuda_bf16.h>
#include <math.h>
#include <stdint.h>

// ---------------- problem constants ----------------
#define N_ROWS   131072
#define DIM      256
#define K_CODES  1024
#define EPS_F    1e-5f
#define TAU      1.4e-4f
#define FIX_CAP  65536

// output layout (float32 elements), reference return order
#define OFF_Q       0
#define OFF_LOSS    33554432
#define OFF_IDX     33554433
#define OFF_NEWEMB  33685505
#define OFF_NCS     33947649
#define OFF_NAVG    33948673

// ---------------- device scratch ----------------
__device__ float  g_ee[K_CODES];
__device__ float  g_counts[K_CODES];
__device__ float  g_embsum[K_CODES*DIM];
__device__ float  g_ncs[K_CODES];
__device__ float  g_ntotal;
__device__ double g_sse;
__device__ double g_ortho;
__device__ int    g_fixcount;
__device__ int    g_fixrows[FIX_CAP];
__device__ int    g_idx[N_ROWS];
__device__ __nv_bfloat16 g_ea[K_CODES*DIM];
__device__ __nv_bfloat16 g_eb[K_CODES*DIM];
__device__ __nv_bfloat16 g_xa[(size_t)N_ROWS*DIM];
__device__ __nv_bfloat16 g_xb[(size_t)N_ROWS*DIM];

// ---------------- PTX helpers (baseline sm_80+ ISA only) ----------------
__device__ __forceinline__ uint32_t smem_to_u32(const void* p) {
    uint32_t a;
    asm("{ .reg .u64 t; cvta.to.shared.u64 t, %1; cvt.u32.u64 %0, t; }" : "=r"(a) : "l"(p));
    return a;
}
#define CP_ASYNC16(dst, src) \
    asm volatile("cp.async.cg.shared.global [%0], [%1], 16;" :: "r"(dst), "l"(src))
#define CP_COMMIT() asm volatile("cp.async.commit_group;" ::: "memory")
#define CP_WAIT1()  asm volatile("cp.async.wait_group 1;" ::: "memory")

#define LDSM_X4(r, addr) \
    asm volatile("ldmatrix.sync.aligned.m8n8.x4.shared.b16 {%0,%1,%2,%3}, [%4];" \
        : "=r"((r)[0]), "=r"((r)[1]), "=r"((r)[2]), "=r"((r)[3]) : "r"(addr))

#define MMA_BF16(c, a, b0, b1) \
    asm volatile("mma.sync.aligned.m16n8k16.row.col.f32.bf16.bf16.f32 " \
        "{%0,%1,%2,%3},{%4,%5,%6,%7},{%8,%9},{%0,%1,%2,%3};" \
        : "+f"((c)[0]), "+f"((c)[1]), "+f"((c)[2]), "+f"((c)[3]) \
        : "r"((a)[0]), "r"((a)[1]), "r"((a)[2]), "r"((a)[3]), "r"(b0), "r"(b1))

__device__ __forceinline__ uint32_t packhi2(float x, float y, float& rx, float& ry) {
    __nv_bfloat16 a = __float2bfloat16_rn(x);
    __nv_bfloat16 b = __float2bfloat16_rn(y);
    rx = x - __bfloat162float(a);
    ry = y - __bfloat162float(b);
    return (uint32_t)__bfloat16_as_ushort(a) | ((uint32_t)__bfloat16_as_ushort(b) << 16);
}
__device__ __forceinline__ uint32_t packlo2(float rx, float ry) {
    __nv_bfloat16 a = __float2bfloat16_rn(rx);
    __nv_bfloat16 b = __float2bfloat16_rn(ry);
    return (uint32_t)__bfloat16_as_ushort(a) | ((uint32_t)__bfloat16_as_ushort(b) << 16);
}

// ---------------- zero scratch ----------------
__global__ void zero_scratch_kernel() {
    int i = blockIdx.x * blockDim.x + threadIdx.x;
    if (i < K_CODES*DIM) g_embsum[i] = 0.f;
    if (i < K_CODES)     g_counts[i] = 0.f;
    if (i == 0) { g_sse = 0.0; g_ortho = 0.0; g_fixcount = 0; }
}

// ---------------- prep codes: ||e||^2 + bf16 hi/lo split ----------------
__global__ void prep_e_kernel(const float* __restrict__ emb) {
    int warp = (blockIdx.x * blockDim.x + threadIdx.x) >> 5;
    int lane = threadIdx.x & 31;
    if (warp >= K_CODES) return;
    const float4* p = (const float4*)(emb + (size_t)warp * DIM);
    float4 v0 = p[lane * 2];
    float4 v1 = p[lane * 2 + 1];
    float s = 0.f;
    s = fmaf(v0.x,v0.x,s); s = fmaf(v0.y,v0.y,s); s = fmaf(v0.z,v0.z,s); s = fmaf(v0.w,v0.w,s);
    s = fmaf(v1.x,v1.x,s); s = fmaf(v1.y,v1.y,s); s = fmaf(v1.z,v1.z,s); s = fmaf(v1.w,v1.w,s);
    float r0,r1,r2,r3,r4,r5,r6,r7;
    uint4 hi, lo;
    hi.x = packhi2(v0.x, v0.y, r0, r1);
    hi.y = packhi2(v0.z, v0.w, r2, r3);
    hi.z = packhi2(v1.x, v1.y, r4, r5);
    hi.w = packhi2(v1.z, v1.w, r6, r7);
    lo.x = packlo2(r0,r1); lo.y = packlo2(r2,r3); lo.z = packlo2(r4,r5); lo.w = packlo2(r6,r7);
    ((uint4*)(g_ea + (size_t)warp * DIM))[lane] = hi;
    ((uint4*)(g_eb + (size_t)warp * DIM))[lane] = lo;
    #pragma unroll
    for (int o = 16; o > 0; o >>= 1) s += __shfl_xor_sync(0xffffffffu, s, o);
    if (lane == 0) g_ee[warp] = s;
}

// ---------------- prep inputs: bf16 hi/lo split ----------------
__global__ void prep_x_kernel(const float* __restrict__ inp) {
    size_t base = ((size_t)blockIdx.x * 256 + threadIdx.x) * 8;
    const float4* p = (const float4*)(inp + base);
    float4 v0 = p[0], v1 = p[1];
    float r0,r1,r2,r3,r4,r5,r6,r7;
    uint4 hi, lo;
    hi.x = packhi2(v0.x, v0.y, r0, r1);
    hi.y = packhi2(v0.z, v0.w, r2, r3);
    hi.z = packhi2(v1.x, v1.y, r4, r5);
    hi.w = packhi2(v1.z, v1.w, r6, r7);
    lo.x = packlo2(r0,r1); lo.y = packlo2(r2,r3); lo.z = packlo2(r4,r5); lo.w = packlo2(r6,r7);
    *(uint4*)(g_xa + base) = hi;
    *(uint4*)(g_xb + base) = lo;
}

// ---------------- HMMA GEMM + top-2 argmin screening ----------------
// smem per buffer: XA 16K | XB 16K | EA 16K | EB 16K  (128 rows x 64 bf16, swizzled)
#define OFB_XA 0
#define OFB_XB 16384
#define OFB_EA 32768
#define OFB_EB 49152
#define BUF_STRIDE 65536
#define SMEM_DYN (2*BUF_STRIDE + 1024)

__device__ __forceinline__ void stage_load(uint32_t sbase, int R0, int st, int tid) {
    int n0 = st >> 2, kc = st & 3;
    uint32_t boff = sbase + (uint32_t)(st & 1) * BUF_STRIDE;
    const __nv_bfloat16* xa = g_xa + ((size_t)R0 << 8) + kc * 64;
    const __nv_bfloat16* xb = g_xb + ((size_t)R0 << 8) + kc * 64;
    const __nv_bfloat16* ea = g_ea + ((size_t)(n0 * 128) << 8) + kc * 64;
    const __nv_bfloat16* eb = g_eb + ((size_t)(n0 * 128) << 8) + kc * 64;
    #pragma unroll
    for (int it = 0; it < 4; it++) {
        int item = tid + it * 256;      // 0..1023
        int r = item >> 3, kb = item & 7;
        uint32_t sw = (((uint32_t)kb * 16u) ^ (((uint32_t)r & 7u) * 16u));
        uint32_t d  = boff + (uint32_t)r * 128u + sw;
        size_t  go  = (size_t)r * DIM + kb * 8;
        CP_ASYNC16(d + OFB_XA, xa + go);
        CP_ASYNC16(d + OFB_XB, xb + go);
        CP_ASYNC16(d + OFB_EA, ea + go);
        CP_ASYNC16(d + OFB_EB, eb + go);
    }
}

__global__ void __launch_bounds__(256, 1)
hmma_gemm_kernel()
{
    extern __shared__ __align__(16) char dsm[];
    uint32_t raw   = smem_to_u32(dsm);
    uint32_t sbase = (raw + 1023u) & ~1023u;
    char*    smema = dsm + (sbase - raw);

    const int tid  = threadIdx.x;
    const int lane = tid & 31, wid = tid >> 5;
    const int wr   = wid >> 2, wc = wid & 3;
    const int R0   = blockIdx.x * 128;
    const int g    = lane >> 2, tig = lane & 3;
    const int q    = lane >> 3, lr  = lane & 7;

    float acc[4][4][4];
    #pragma unroll
    for (int a = 0; a < 4; a++)
        #pragma unroll
        for (int b = 0; b < 4; b++)
            #pragma unroll
            for (int c = 0; c < 4; c++) acc[a][b][c] = 0.f;

    float rs1[8], rs2[8]; int ri[8];
    #pragma unroll
    for (int j = 0; j < 8; j++) { rs1[j] = 3.0e38f; rs2[j] = 3.0e38f; ri[j] = 0x7fffffff; }

    stage_load(sbase, R0, 0, tid);
    CP_COMMIT();

    for (int s = 0; s < 32; s++) {
        if (s + 1 < 32) stage_load(sbase, R0, s + 1, tid);
        CP_COMMIT();
        CP_WAIT1();
        __syncthreads();

        uint32_t boff = sbase + (uint32_t)(s & 1) * BUF_STRIDE;
        #pragma unroll
        for (int ks = 0; ks < 4; ks++) {
            uint32_t axa[16], axb[16];
            int rowb = wr * 64 + lr + ((q & 1) << 3);
            int kbA  = ks * 2 + (q >> 1);
            uint32_t swA = (((uint32_t)kbA * 16u) ^ ((uint32_t)lr * 16u));
            #pragma unroll
            for (int mf = 0; mf < 4; mf++) {
                uint32_t ad = boff + (uint32_t)(rowb + mf * 16) * 128u + swA;
                LDSM_X4(&axa[mf * 4], ad + OFB_XA);
                LDSM_X4(&axb[mf * 4], ad + OFB_XB);
            }
            uint32_t bea[8], beb[8];
            int kbB = ks * 2 + (q & 1);
            uint32_t swB = (((uint32_t)kbB * 16u) ^ ((uint32_t)lr * 16u));
            #pragma unroll
            for (int np = 0; np < 2; np++) {
                int code = wc * 32 + np * 16 + lr + ((q >> 1) << 3);
                uint32_t ed = boff + (uint32_t)code * 128u + swB;
                LDSM_X4(&bea[np * 4], ed + OFB_EA);
                LDSM_X4(&beb[np * 4], ed + OFB_EB);
            }
            #pragma unroll
            for (int mf = 0; mf < 4; mf++)
                #pragma unroll
                for (int nf = 0; nf < 4; nf++) {
                    int bo = (nf >> 1) * 4 + (nf & 1) * 2;
                    MMA_BF16(acc[mf][nf], &axa[mf * 4], bea[bo], bea[bo + 1]);
                    MMA_BF16(acc[mf][nf], &axa[mf * 4], beb[bo], beb[bo + 1]);
                    MMA_BF16(acc[mf][nf], &axb[mf * 4], bea[bo], bea[bo + 1]);
                }
        }

        if ((s & 3) == 3) {
            int n0 = s >> 2;
            float ee8[8];
            #pragma unroll
            for (int nf = 0; nf < 4; nf++) {
                int code = n0 * 128 + wc * 32 + nf * 8 + tig * 2;
                ee8[nf * 2]     = __ldg(&g_ee[code]);
                ee8[nf * 2 + 1] = __ldg(&g_ee[code + 1]);
            }
            #pragma unroll
            for (int mf = 0; mf < 4; mf++)
                #pragma unroll
                for (int h = 0; h < 2; h++) {
                    int j = mf * 2 + h;
                    float b1 = 3.0e38f, b2 = 3.0e38f; int bi = 0;
                    #pragma unroll
                    for (int nf = 0; nf < 4; nf++) {
                        int code = n0 * 128 + wc * 32 + nf * 8 + tig * 2;
                        float s0 = fmaf(-2.f, acc[mf][nf][h * 2],     ee8[nf * 2]);
                        float s1 = fmaf(-2.f, acc[mf][nf][h * 2 + 1], ee8[nf * 2 + 1]);
                        if (s0 < b1) { b2 = b1; b1 = s0; bi = code; }
                        else if (s0 < b2) b2 = s0;
                        if (s1 < b1) { b2 = b1; b1 = s1; bi = code + 1; }
                        else if (s1 < b2) b2 = s1;
                    }
                    #pragma unroll
                    for (int off = 1; off <= 2; off <<= 1) {
                        float o1 = __shfl_xor_sync(0xffffffffu, b1, off);
                        float o2 = __shfl_xor_sync(0xffffffffu, b2, off);
                        int   oi = __shfl_xor_sync(0xffffffffu, bi, off);
                        if (o1 < b1) { b2 = fminf(b1, o2); b1 = o1; bi = oi; }
                        else         { b2 = fminf(b2, o1); }
                    }
                    if (b1 < rs1[j]) { rs2[j] = fminf(rs1[j], b2); rs1[j] = b1; ri[j] = bi; }
                    else             { rs2[j] = fminf(rs2[j], b1); }
                }
            #pragma unroll
            for (int a = 0; a < 4; a++)
                #pragma unroll
                for (int b = 0; b < 4; b++)
                    #pragma unroll
                    for (int c = 0; c < 4; c++) acc[a][b][c] = 0.f;
        }
        __syncthreads();
    }

    // final cross-warp merge (alias chunk smem: 128 rows x 4 warps x {s1,s2,i1})
    float* fs1 = (float*)smema;
    float* fs2 = (float*)(smema + 2048);
    int*   fi1 = (int*)  (smema + 4096);
    #pragma unroll
    for (int mf = 0; mf < 4; mf++)
        #pragma unroll
        for (int h = 0; h < 2; h++) {
            int j = mf * 2 + h;
            int row = wr * 64 + mf * 16 + h * 8 + g;
            fs1[row * 4 + wc] = rs1[j];
            fs2[row * 4 + wc] = rs2[j];
            fi1[row * 4 + wc] = ri[j];
        }
    __syncthreads();
    if (tid < 128) {
        float b1 = 3.0e38f, b2 = 3.0e38f; int bi = 0;
        #pragma unroll
        for (int w = 0; w < 4; w++) {
            float o1 = fs1[tid * 4 + w], o2 = fs2[tid * 4 + w];
            int   oi = fi1[tid * 4 + w];
            if (o1 < b1) { b2 = fminf(b1, o2); b1 = o1; bi = oi; }
            else         { b2 = fminf(b2, o1); }
        }
        g_idx[R0 + tid] = bi;
        if (b2 - b1 < TAU) {
            int p = atomicAdd(&g_fixcount, 1);
            if (p < FIX_CAP) g_fixrows[p] = R0 + tid;
        }
    }
}

// ---------------- exact fp32 rescore for ambiguous rows ----------------
__global__ void __launch_bounds__(256)
rescore_kernel(const float* __restrict__ inp, const float* __restrict__ emb)
{
    __shared__ float sx[8][256];
    __shared__ float sxr[8];
    __shared__ float sd[8 * 256];
    __shared__ int   si[8 * 256];

    int n = g_fixcount; if (n > FIX_CAP) n = FIX_CAP;
    int base = blockIdx.x * 8;
    if (base >= n) return;
    int nrows = n - base; if (nrows > 8) nrows = 8;

    const int tid = threadIdx.x;
    const int wid = tid >> 5, lane = tid & 31;

    for (int e = tid; e < nrows * 64; e += 256) {
        int r = e >> 6, c = e & 63;
        ((float4*)sx[r])[c] = ((const float4*)(inp + (size_t)g_fixrows[base + r] * DIM))[c];
    }
    __syncthreads();
    if (wid < 8) {
        float s = 0.f;
        #pragma unroll
        for (int qq = 0; qq < 8; qq++) { float v = sx[wid][lane * 8 + qq]; s = fmaf(v, v, s); }
        #pragma unroll
        for (int o = 16; o > 0; o >>= 1) s += __shfl_xor_sync(0xffffffffu, s, o);
        if (lane == 0) sxr[wid] = s;
    }
    __syncthreads();

    float bd[8]; int bi[8];
    #pragma unroll
    for (int r = 0; r < 8; r++) { bd[r] = 3.0e38f; bi[r] = 0x7fffffff; }

    for (int it = 0; it < 4; it++) {
        int code = tid + it * 256;
        const float4* er = (const float4*)(emb + (size_t)code * DIM);
        float dot[8];
        #pragma unroll
        for (int r = 0; r < 8; r++) dot[r] = 0.f;
        for (int k4 = 0; k4 < 64; k4++) {
            float4 ev = er[k4];
            #pragma unroll
            for (int r = 0; r < 8; r++) {
                float4 xv = ((float4*)sx[r])[k4];
                dot[r] = fmaf(ev.x, xv.x, dot[r]);
                dot[r] = fmaf(ev.y, xv.y, dot[r]);
                dot[r] = fmaf(ev.z, xv.z, dot[r]);
                dot[r] = fmaf(ev.w, xv.w, dot[r]);
            }
        }
        float ec = g_ee[code];
        #pragma unroll
        for (int r = 0; r < 8; r++) {
            float d = (sxr[r] + ec) - 2.0f * dot[r];
            if (d < bd[r]) { bd[r] = d; bi[r] = code; }
        }
    }
    #pragma unroll
    for (int r = 0; r < 8; r++) { sd[r * 256 + tid] = bd[r]; si[r * 256 + tid] = bi[r]; }
    __syncthreads();
    for (int s = 128; s > 0; s >>= 1) {
        if (tid < s) {
            #pragma unroll
            for (int r = 0; r < 8; r++) {
                float d1 = sd[r*256 + tid],     d2 = sd[r*256 + tid + s];
                int   j1 = si[r*256 + tid],     j2 = si[r*256 + tid + s];
                if (d2 < d1 || (d2 == d1 && j2 < j1)) { sd[r*256 + tid] = d2; si[r*256 + tid] = j2; }
            }
        }
        __syncthreads();
    }
    if (tid < nrows) g_idx[g_fixrows[base + tid]] = si[tid * 256];
}

// ---------------- epilogue: gather + ST output + MSE + segment scatter ----------------
__global__ void __launch_bounds__(256)
epilogue_kernel(const float* __restrict__ inp, const float* __restrict__ emb,
                float* __restrict__ out)
{
    __shared__ int besti[128];
    __shared__ double dred[256];
    const int tid = threadIdx.x;
    const int R0  = blockIdx.x * 128;
    if (tid < 128) {
        int v = g_idx[R0 + tid];
        besti[tid] = v;
        out[OFF_IDX + R0 + tid] = (float)v;
    }
    __syncthreads();

    double sse = 0.0;
    const float4* inp4 = (const float4*)inp;
    const float4* emb4 = (const float4*)emb;
    float4* out4 = (float4*)(out + OFF_Q);
    #pragma unroll 4
    for (int j = 0; j < 32; j++) {
        int e4  = tid + j * 256;
        int r   = e4 >> 6;
        int c4  = e4 & 63;
        int idx = besti[r];
        float4 ev = emb4[idx * 64 + c4];
        float4 xv = inp4[(size_t)(R0 + r) * 64 + c4];
        float4 qv;
        qv.x = xv.x + (ev.x - xv.x);
        qv.y = xv.y + (ev.y - xv.y);
        qv.z = xv.z + (ev.z - xv.z);
        qv.w = xv.w + (ev.w - xv.w);
        out4[(size_t)(R0 + r) * 64 + c4] = qv;
        float d0 = ev.x - xv.x, d1 = ev.y - xv.y, d2 = ev.z - xv.z, d3 = ev.w - xv.w;
        sse += (double)d0*d0 + (double)d1*d1 + (double)d2*d2 + (double)d3*d3;
        float* es = &g_embsum[idx * DIM + c4 * 4];
        atomicAdd(es + 0, xv.x);
        atomicAdd(es + 1, xv.y);
        atomicAdd(es + 2, xv.z);
        atomicAdd(es + 3, xv.w);
        if (c4 == 0) atomicAdd(&g_counts[idx], 1.0f);
    }
    dred[tid] = sse;
    __syncthreads();
    #pragma unroll
    for (int s = 128; s > 0; s >>= 1) {
        if (tid < s) dred[tid] += dred[tid + s];
        __syncthreads();
    }
    if (tid == 0) atomicAdd(&g_sse, dred[0]);
}

// ---------------- ortho via ||E^T E||_F^2 ----------------
__global__ void gram_kernel(const float* __restrict__ emb) {
    __shared__ float sA[64][16];
    __shared__ float sB[64][16];
    __shared__ double sred[256];
    int tx = threadIdx.x & 15;
    int ty = threadIdx.x >> 4;
    int a0 = blockIdx.y * 16;
    int b0 = blockIdx.x * 16;
    float acc = 0.f;
    for (int k0 = 0; k0 < K_CODES; k0 += 64) {
        __syncthreads();
        #pragma unroll
        for (int i = 0; i < 4; i++) {
            int e = threadIdx.x + i * 256;
            int kr = e >> 4, c = e & 15;
            sA[kr][c] = emb[(size_t)(k0 + kr) * DIM + a0 + c];
            sB[kr][c] = emb[(size_t)(k0 + kr) * DIM + b0 + c];
        }
        __syncthreads();
        #pragma unroll 8
        for (int kk = 0; kk < 64; kk++)
            acc = fmaf(sA[kk][ty], sB[kk][tx], acc);
    }
    sred[threadIdx.x] = (double)acc * (double)acc;
    __syncthreads();
    #pragma unroll
    for (int s = 128; s > 0; s >>= 1) {
        if (threadIdx.x < s) sred[threadIdx.x] += sred[threadIdx.x + s];
        __syncthreads();
    }
    if (threadIdx.x == 0) atomicAdd(&g_ortho, sred[0]);
}

// ---------------- EMA finalize ----------------
__global__ void ema_a_kernel(const float* __restrict__ ema_cs, float* __restrict__ out) {
    __shared__ double sred[1024];
    int k = threadIdx.x;
    float ncs = 0.99f * ema_cs[k] + 0.01f * g_counts[k];
    out[OFF_NCS + k] = ncs;
    g_ncs[k] = ncs;
    sred[k] = (double)ncs;
    __syncthreads();
    #pragma unroll
    for (int s = 512; s > 0; s >>= 1) {
        if (k < s) sred[k] += sred[k + s];
        __syncthreads();
    }
    if (k == 0) g_ntotal = (float)sred[0] + EPS_F;
}
__global__ void ema_b_kernel(const float* __restrict__ ema_avg, float* __restrict__ out) {
    int k = blockIdx.x;
    int d = threadIdx.x;
    int i = k * DIM + d;
    float navg = 0.99f * ema_avg[i] + 0.01f * g_embsum[i];
    out[OFF_NAVG + i] = navg;
    float cs = (g_ncs[k] + EPS_F) / g_ntotal;
    out[OFF_NEWEMB + i] = navg / cs;
}

// ---------------- loss ----------------
__global__ void loss_fin_kernel(float* __restrict__ out) {
    __shared__ double sred[256];
    double s = 0.0;
    for (int k = threadIdx.x; k < K_CODES; k += 256) {
        double e = (double)g_ee[k];
        s += e * e;
    }
    sred[threadIdx.x] = s;
    __syncthreads();
    #pragma unroll
    for (int t = 128; t > 0; t >>= 1) {
        if (threadIdx.x < t) sred[threadIdx.x] += sred[threadIdx.x + t];
        __syncthreads();
    }
    if (threadIdx.x == 0) {
        double o2 = g_ortho - sred[0];
        if (o2 < 0.0) o2 = 0.0;
        float ortho = sqrtf((float)o2);
        float m = (float)(g_sse / (double)((size_t)N_ROWS * DIM));
        out[OFF_LOSS] = (m + 0.25f * m) + 0.09f * ortho;
    }
}

// ---------------- launch ----------------
extern "C" void kernel_launch(void* const* d_in, const int* in_sizes, int n_in,
                              void* d_out, int out_size)
{
    const float* inp     = (const float*)d_in[0];
    const float* emb     = (const float*)d_in[1];
    const float* ema_cs  = (const float*)d_in[2];
    const float* ema_avg = (const float*)d_in[3];
    float* out = (float*)d_out;

    static int attr_done = 0;
    if (!attr_done) {
        cudaFuncSetAttribute(hmma_gemm_kernel,
                             cudaFuncAttributeMaxDynamicSharedMemorySize, SMEM_DYN);
        attr_done = 1;
    }

    zero_scratch_kernel<<<K_CODES, 256>>>();
    prep_e_kernel<<<K_CODES / 8, 256>>>(emb);
    prep_x_kernel<<<(N_ROWS * DIM) / (256 * 8), 256>>>(inp);
    hmma_gemm_kernel<<<N_ROWS / 128, 256, SMEM_DYN>>>();
    rescore_kernel<<<FIX_CAP / 8, 256>>>(inp, emb);
    epilogue_kernel<<<N_ROWS / 128, 256>>>(inp, emb, out);
    gram_kernel<<<dim3(16, 16), 256>>>(emb);
    ema_a_kernel<<<1, 1024>>>(ema_cs, out);
    ema_b_kernel<<<K_CODES, 256>>>(ema_avg, out);
    loss_fin_kernel<<<1, 256>>>(out);
}